// round 6
// baseline (speedup 1.0000x reference)
#include <cuda_runtime.h>
#include <math.h>

#define NPTS  16384
#define R2    (1.0f / 256.0f)
#define NCELL 32768         // 8 clouds * 16^3, cell edge = r = 1/16
#define NBLK  512
#define NTHR  256           // 8 lanes per point, 32 points per block
#define CAPB  16            // bucket slots per cell (lambda ~0.5)
#define CAPN  32            // per-point neighbor capacity (lambda ~2.1)

// ---- scratch (static __device__; no allocation allowed) ----
__device__ int    g_cell_cnt[NCELL];          // zero-init; re-cleared each run
__device__ float4 g_bucket[NCELL * CAPB];     // x,y,z, idx-as-float
__device__ float  g_h0b[NPTS * 16];           // per-layer  x@W1x + b1
__device__ float  g_h0c[NPTS * 32];

// ---- software grid barrier (all NBLK blocks co-resident by launch_bounds) ----
__device__ int          g_bar_count = 0;
__device__ volatile int g_bar_gen   = 0;

__device__ __forceinline__ void grid_barrier() {
    __syncthreads();
    if (threadIdx.x == 0) {
        __threadfence();
        const int gen = g_bar_gen;
        if (atomicAdd(&g_bar_count, 1) == NBLK - 1) {
            g_bar_count = 0;
            __threadfence();
            g_bar_gen = gen + 1;
        } else {
            while (g_bar_gen == gen) __nanosleep(32);
        }
        __threadfence();
    }
    __syncthreads();
}

__device__ __forceinline__ float celu1(float v) {
    return v > 0.0f ? v : expm1f(v);
}

// ---------------------------------------------------------------------------
// One persistent kernel, 3 grid barriers:
//   P1 bucket-build + output copies | P2 query with INLINE layer a | P3 layer b
//   | P4 layer c.  8 lanes per point; neighbor lists cached in smem.
// Output tuple layout: out = [pos(3N) | feat(32N) | batch(N)].
// ---------------------------------------------------------------------------
__global__ __launch_bounds__(NTHR, 4) void fused_kernel(
    const float* __restrict__ pos, const int* __restrict__ batch,
    const float* __restrict__ W1a, const float* __restrict__ b1a,
    const float* __restrict__ W2a, const float* __restrict__ b2a,
    const float* __restrict__ W1b, const float* __restrict__ b1b,
    const float* __restrict__ W2b, const float* __restrict__ b2b,
    const float* __restrict__ W1c, const float* __restrict__ b1c,
    const float* __restrict__ W2c, const float* __restrict__ b2c,
    float* __restrict__ out)
{
    // weights in smem (broadcast LDS)
    __shared__ float sWax[24],  sWar[24],   sB1a[8];
    __shared__ float sW2a[64],  sB2a[8],    sWbx[128], sB1b[16];
    __shared__ float sWbr[48],  sW2b[256],  sB2b[16],  sWcx[512], sB1c[32];
    __shared__ float sWcr[96],  sW2c[1024], sB2c[32];
    __shared__ int    s_cnt[32];
    __shared__ int    s_nidx[32 * CAPN];
    __shared__ float4 s_nrel[32 * CAPN];

    const int tid = threadIdx.x;
    const int blk = blockIdx.x;
    const int gtid = blk * NTHR + tid;
    const int r = tid & 7;        // lane within point-group (0..7)
    const int p = tid >> 3;       // point within block (0..31)
    const int i = blk * 32 + p;   // global point id

    for (int k = tid; k < 24;   k += NTHR) sWax[k] = W1a[k];             // x rows
    for (int k = tid; k < 24;   k += NTHR) sWar[k] = W1a[24 + k];        // rel rows
    for (int k = tid; k < 8;    k += NTHR) sB1a[k] = b1a[k];
    for (int k = tid; k < 64;   k += NTHR) sW2a[k] = W2a[k];
    for (int k = tid; k < 8;    k += NTHR) sB2a[k] = b2a[k];
    for (int k = tid; k < 128;  k += NTHR) sWbx[k] = W1b[k];             // x rows
    for (int k = tid; k < 16;   k += NTHR) sB1b[k] = b1b[k];
    for (int k = tid; k < 48;   k += NTHR) sWbr[k] = W1b[128 + k];       // rel rows
    for (int k = tid; k < 256;  k += NTHR) sW2b[k] = W2b[k];
    for (int k = tid; k < 16;   k += NTHR) sB2b[k] = b2b[k];
    for (int k = tid; k < 512;  k += NTHR) sWcx[k] = W1c[k];             // x rows
    for (int k = tid; k < 32;   k += NTHR) sB1c[k] = b1c[k];
    for (int k = tid; k < 96;   k += NTHR) sWcr[k] = W1c[512 + k];       // rel rows
    for (int k = tid; k < 1024; k += NTHR) sW2c[k] = W2c[k];
    for (int k = tid; k < 32;   k += NTHR) sB2c[k] = b2c[k];

    // ---- P1: bucket insert + output pos/batch copies ----
    const float px = pos[3 * i + 0];
    const float py = pos[3 * i + 1];
    const float pz = pos[3 * i + 2];
    const float si = fmaf(pz, pz, fmaf(py, py, px * px));
    const int bb = batch[i];
    const int cx0 = min(15, max(0, (int)(px * 16.0f)));
    const int cy0 = min(15, max(0, (int)(py * 16.0f)));
    const int cz0 = min(15, max(0, (int)(pz * 16.0f)));
    const int c = (bb << 12) | (cz0 << 8) | (cy0 << 4) | cx0;

    if (r == 0) {
        out[3 * i + 0] = px;
        out[3 * i + 1] = py;
        out[3 * i + 2] = pz;
        out[(size_t)NPTS * 35 + i] = (float)bb;
    } else if (r == 1) {
        const int slot = atomicAdd(&g_cell_cnt[c], 1);
        if (slot < CAPB)
            g_bucket[c * CAPB + slot] = make_float4(px, py, pz, __int_as_float(i));
    }
    grid_barrier();

    // ---- P2: radius query (27-cell stencil, lanes split cells) + INLINE layer a
    int cnt;
    {
        if (r == 0) s_cnt[p] = 0;
        __syncwarp();

        const int cb = c & 0xF000;

        // resolve this lane's <=4 cells and prefetch their counts (MLP=4)
        int cells[4], cnts[4];
#pragma unroll
        for (int t = 0; t < 4; ++t) {
            const int k = r + 8 * t;
            bool ok = (k < 27);
            const int z = cz0 + k / 9 - 1;
            const int y = cy0 + (k / 3) % 3 - 1;
            const int x = cx0 + k % 3 - 1;
            ok = ok && ((unsigned)(z | y | x) <= 15u);
            cells[t] = ok ? (cb | (z << 8) | (y << 4) | x) : 0;
            cnts[t]  = ok ? min(g_cell_cnt[cells[t]], CAPB) : 0;
        }

        float acc[8];
#pragma unroll
        for (int m = 0; m < 8; ++m) acc[m] = -INFINITY;

#pragma unroll
        for (int t = 0; t < 4; ++t) {
            const int base = cells[t] * CAPB;
            for (int e = 0; e < cnts[t]; ++e) {
                const float4 q = g_bucket[base + e];
                const float sj  = fmaf(q.z, q.z, fmaf(q.y, q.y, q.x * q.x));
                const float dot = px * q.x + py * q.y + pz * q.z;
                const float d2  = si + sj - 2.0f * dot;   // reference's formula
                if (d2 <= R2) {
                    const int jo = __float_as_int(q.w);
                    const float rx = q.x - px, ry = q.y - py, rz = q.z - pz;
                    const int slot = atomicAdd(&s_cnt[p], 1);
                    if (slot < CAPN) {
                        s_nidx[p * CAPN + slot] = jo;
                        s_nrel[p * CAPN + slot] = make_float4(rx, ry, rz, 0.0f);
                    }
                    // layer-a message computed inline from bucket data (no gather)
#pragma unroll
                    for (int m = 0; m < 8; ++m) {
                        float h = sB1a[m];
                        h = fmaf(q.x, sWax[0 * 8 + m], h);
                        h = fmaf(q.y, sWax[1 * 8 + m], h);
                        h = fmaf(q.z, sWax[2 * 8 + m], h);
                        h = fmaf(rx,  sWar[0 * 8 + m], h);
                        h = fmaf(ry,  sWar[1 * 8 + m], h);
                        h = fmaf(rz,  sWar[2 * 8 + m], h);
                        acc[m] = fmaxf(acc[m], fmaxf(h, 0.0f));
                    }
                }
            }
        }
        __syncwarp();
#pragma unroll
        for (int m = 0; m < 8; ++m) {
            acc[m] = fmaxf(acc[m], __shfl_xor_sync(0xffffffffu, acc[m], 1, 8));
            acc[m] = fmaxf(acc[m], __shfl_xor_sync(0xffffffffu, acc[m], 2, 8));
            acc[m] = fmaxf(acc[m], __shfl_xor_sync(0xffffffffu, acc[m], 4, 8));
        }
        cnt = min(s_cnt[p], CAPN);

        // epilogue: output o = r, then h0b channels 2r, 2r+1 via shfl
        float v = sB2a[r];
#pragma unroll
        for (int m = 0; m < 8; ++m) v = fmaf(acc[m], sW2a[m * 8 + r], v);
        v = celu1(v);

        float h0 = sB1b[2 * r], h1 = sB1b[2 * r + 1];
#pragma unroll
        for (int o = 0; o < 8; ++o) {
            const float vo = __shfl_sync(0xffffffffu, v, o, 8);
            h0 = fmaf(vo, sWbx[o * 16 + 2 * r + 0], h0);
            h1 = fmaf(vo, sWbx[o * 16 + 2 * r + 1], h1);
        }
        *(float2*)&g_h0b[(size_t)i * 16 + 2 * r] = make_float2(h0, h1);
    }
    grid_barrier();

    // ---- P3: layer b (channel-split: lane owns channels 2r, 2r+1) ----
    {
        if (gtid < NCELL) g_cell_cnt[gtid] = 0;   // reset for next graph replay

        float a0 = -INFINITY, a1 = -INFINITY;
        for (int n = 0; n < cnt; ++n) {
            const float4 rel = s_nrel[p * CAPN + n];
            const int j = s_nidx[p * CAPN + n];
            const float2 hb = *(const float2*)&g_h0b[(size_t)j * 16 + 2 * r];
            float h = hb.x;
            h = fmaf(rel.x, sWbr[0 * 16 + 2 * r], h);
            h = fmaf(rel.y, sWbr[1 * 16 + 2 * r], h);
            h = fmaf(rel.z, sWbr[2 * 16 + 2 * r], h);
            a0 = fmaxf(a0, fmaxf(h, 0.0f));
            h = hb.y;
            h = fmaf(rel.x, sWbr[0 * 16 + 2 * r + 1], h);
            h = fmaf(rel.y, sWbr[1 * 16 + 2 * r + 1], h);
            h = fmaf(rel.z, sWbr[2 * 16 + 2 * r + 1], h);
            a1 = fmaxf(a1, fmaxf(h, 0.0f));
        }
        __syncwarp();

        // v[2r], v[2r+1] = celu(accfull @ W2b + b2b), accfull gathered by shfl
        float v0 = sB2b[2 * r], v1 = sB2b[2 * r + 1];
#pragma unroll
        for (int mm = 0; mm < 8; ++mm) {
            const float am0 = __shfl_sync(0xffffffffu, a0, mm, 8);  // ch 2mm
            const float am1 = __shfl_sync(0xffffffffu, a1, mm, 8);  // ch 2mm+1
            v0 = fmaf(am0, sW2b[(2 * mm + 0) * 16 + 2 * r + 0], v0);
            v0 = fmaf(am1, sW2b[(2 * mm + 1) * 16 + 2 * r + 0], v0);
            v1 = fmaf(am0, sW2b[(2 * mm + 0) * 16 + 2 * r + 1], v1);
            v1 = fmaf(am1, sW2b[(2 * mm + 1) * 16 + 2 * r + 1], v1);
        }
        v0 = celu1(v0);
        v1 = celu1(v1);

        // h0c channels 4r..4r+3 = b1c + v @ W1c[0:16]
        float c0 = sB1c[4 * r + 0], c1 = sB1c[4 * r + 1];
        float c2 = sB1c[4 * r + 2], c3 = sB1c[4 * r + 3];
#pragma unroll
        for (int oo = 0; oo < 8; ++oo) {
            const float w0 = __shfl_sync(0xffffffffu, v0, oo, 8);   // out 2oo
            const float w1 = __shfl_sync(0xffffffffu, v1, oo, 8);   // out 2oo+1
            c0 = fmaf(w0, sWcx[(2 * oo) * 32 + 4 * r + 0], c0);
            c1 = fmaf(w0, sWcx[(2 * oo) * 32 + 4 * r + 1], c1);
            c2 = fmaf(w0, sWcx[(2 * oo) * 32 + 4 * r + 2], c2);
            c3 = fmaf(w0, sWcx[(2 * oo) * 32 + 4 * r + 3], c3);
            c0 = fmaf(w1, sWcx[(2 * oo + 1) * 32 + 4 * r + 0], c0);
            c1 = fmaf(w1, sWcx[(2 * oo + 1) * 32 + 4 * r + 1], c1);
            c2 = fmaf(w1, sWcx[(2 * oo + 1) * 32 + 4 * r + 2], c2);
            c3 = fmaf(w1, sWcx[(2 * oo + 1) * 32 + 4 * r + 3], c3);
        }
        *(float4*)&g_h0c[(size_t)i * 32 + 4 * r] = make_float4(c0, c1, c2, c3);
    }
    grid_barrier();

    // ---- P4: layer c (channel-split: lane owns channels 4r..4r+3) ----
    {
        float acc[4];
#pragma unroll
        for (int m = 0; m < 4; ++m) acc[m] = -INFINITY;

        for (int n = 0; n < cnt; ++n) {
            const float4 rel = s_nrel[p * CAPN + n];
            const int j = s_nidx[p * CAPN + n];
            const float4 hc = *(const float4*)&g_h0c[(size_t)j * 32 + 4 * r];
            const float hj[4] = {hc.x, hc.y, hc.z, hc.w};
#pragma unroll
            for (int m = 0; m < 4; ++m) {
                float h = hj[m];
                h = fmaf(rel.x, sWcr[0 * 32 + 4 * r + m], h);
                h = fmaf(rel.y, sWcr[1 * 32 + 4 * r + m], h);
                h = fmaf(rel.z, sWcr[2 * 32 + 4 * r + m], h);
                acc[m] = fmaxf(acc[m], fmaxf(h, 0.0f));
            }
        }
        __syncwarp();

        float s0 = sB2c[4 * r + 0], s1 = sB2c[4 * r + 1];
        float s2 = sB2c[4 * r + 2], s3 = sB2c[4 * r + 3];
#pragma unroll
        for (int mm = 0; mm < 8; ++mm) {
            float am[4];
#pragma unroll
            for (int k = 0; k < 4; ++k)
                am[k] = __shfl_sync(0xffffffffu, acc[k], mm, 8);    // ch 4mm+k
#pragma unroll
            for (int k = 0; k < 4; ++k) {
                const int row = 4 * mm + k;
                s0 = fmaf(am[k], sW2c[row * 32 + 4 * r + 0], s0);
                s1 = fmaf(am[k], sW2c[row * 32 + 4 * r + 1], s1);
                s2 = fmaf(am[k], sW2c[row * 32 + 4 * r + 2], s2);
                s3 = fmaf(am[k], sW2c[row * 32 + 4 * r + 3], s3);
            }
        }
        float4* dst = (float4*)(out + (size_t)NPTS * 3 + (size_t)i * 32 + 4 * r);
        *dst = make_float4(celu1(s0), celu1(s1), celu1(s2), celu1(s3));
    }
}

// ---------------------------------------------------------------------------
// Launch. Inputs: 0 pos | 1 rgb (unused) | 2 batch |
//  3 W1a[6,8] 4 b1a 5 W2a 6 b2a | 7 W1b[11,16] 8 b1b 9 W2b 10 b2b
// 11 W1c[19,32] 12 b1c 13 W2c 14 b2c
// Output: [pos(3N) | feat(32N) | batch(N)] float32.
// ---------------------------------------------------------------------------
extern "C" void kernel_launch(void* const* d_in, const int* in_sizes, int n_in,
                              void* d_out, int out_size)
{
    fused_kernel<<<NBLK, NTHR>>>(
        (const float*)d_in[0], (const int*)d_in[2],
        (const float*)d_in[3],  (const float*)d_in[4],
        (const float*)d_in[5],  (const float*)d_in[6],
        (const float*)d_in[7],  (const float*)d_in[8],
        (const float*)d_in[9],  (const float*)d_in[10],
        (const float*)d_in[11], (const float*)d_in[12],
        (const float*)d_in[13], (const float*)d_in[14],
        (float*)d_out);
}

// round 7
// speedup vs baseline: 1.4628x; 1.4628x over previous
#include <cuda_runtime.h>
#include <math.h>

#define NPTS  16384
#define R2    (1.0f / 256.0f)
#define NCELL 32768         // 8 clouds * 16^3, cell edge = r = 1/16
#define NBLK  512
#define NTHR  256           // 8 lanes per point, 32 points per block
#define CAPB  16            // bucket slots per cell (lambda ~0.5)
#define CAPN  32            // per-point neighbor capacity (lambda ~2.1)

// ---- scratch (static __device__; no allocation allowed) ----
__device__ int    g_cell_cnt[NCELL];          // zero-init; re-cleared each run
__device__ float4 g_bucket[NCELL * CAPB];     // x,y,z, idx-as-float
__device__ float  g_h0a[NPTS * 8];            // per-layer  x@W1x + b1
__device__ float  g_h0b[NPTS * 16];
__device__ float  g_h0c[NPTS * 32];

// ---- software grid barrier (all NBLK blocks co-resident by launch_bounds) ----
__device__ int          g_bar_count = 0;
__device__ volatile int g_bar_gen   = 0;

__device__ __forceinline__ void grid_barrier() {
    __syncthreads();
    if (threadIdx.x == 0) {
        __threadfence();
        const int gen = g_bar_gen;
        if (atomicAdd(&g_bar_count, 1) == NBLK - 1) {
            g_bar_count = 0;
            __threadfence();
            g_bar_gen = gen + 1;
        } else {
            while (g_bar_gen == gen) __nanosleep(32);
        }
        __threadfence();
    }
    __syncthreads();
}

__device__ __forceinline__ float celu1(float v) {
    return v > 0.0f ? v : expm1f(v);
}

// ---------------------------------------------------------------------------
// One persistent kernel, 3 grid barriers:
//   P1 bucket-build + h0a + output copies | P2 query then channel-split layer a
//   | P3 layer b | P4 layer c.  8 lanes per point; neighbor lists in smem.
// Output tuple layout: out = [pos(3N) | feat(32N) | batch(N)].
// ---------------------------------------------------------------------------
__global__ __launch_bounds__(NTHR, 4) void fused_kernel(
    const float* __restrict__ pos, const int* __restrict__ batch,
    const float* __restrict__ W1a, const float* __restrict__ b1a,
    const float* __restrict__ W2a, const float* __restrict__ b2a,
    const float* __restrict__ W1b, const float* __restrict__ b1b,
    const float* __restrict__ W2b, const float* __restrict__ b2b,
    const float* __restrict__ W1c, const float* __restrict__ b1c,
    const float* __restrict__ W2c, const float* __restrict__ b2c,
    float* __restrict__ out)
{
    // weights in smem (broadcast LDS; inner-loop weights hoisted to regs below)
    __shared__ float sWar[24],  sW2a[64],   sB2a[8],  sWbx[128], sB1b[16];
    __shared__ float sWbr[48],  sW2b[256],  sB2b[16], sWcx[512], sB1c[32];
    __shared__ float sWcr[96],  sW2c[1024], sB2c[32];
    __shared__ int    s_cnt[32];
    __shared__ int    s_nidx[32 * CAPN];
    __shared__ float4 s_nrel[32 * CAPN];

    const int tid = threadIdx.x;
    const int blk = blockIdx.x;
    const int gtid = blk * NTHR + tid;
    const int r = tid & 7;        // lane within point-group (0..7)
    const int p = tid >> 3;       // point within block (0..31)
    const int i = blk * 32 + p;   // global point id

    for (int k = tid; k < 24;   k += NTHR) sWar[k] = W1a[24 + k];        // rel rows
    for (int k = tid; k < 64;   k += NTHR) sW2a[k] = W2a[k];
    for (int k = tid; k < 8;    k += NTHR) sB2a[k] = b2a[k];
    for (int k = tid; k < 128;  k += NTHR) sWbx[k] = W1b[k];             // x rows
    for (int k = tid; k < 16;   k += NTHR) sB1b[k] = b1b[k];
    for (int k = tid; k < 48;   k += NTHR) sWbr[k] = W1b[128 + k];       // rel rows
    for (int k = tid; k < 256;  k += NTHR) sW2b[k] = W2b[k];
    for (int k = tid; k < 16;   k += NTHR) sB2b[k] = b2b[k];
    for (int k = tid; k < 512;  k += NTHR) sWcx[k] = W1c[k];             // x rows
    for (int k = tid; k < 32;   k += NTHR) sB1c[k] = b1c[k];
    for (int k = tid; k < 96;   k += NTHR) sWcr[k] = W1c[512 + k];       // rel rows
    for (int k = tid; k < 1024; k += NTHR) sW2c[k] = W2c[k];
    for (int k = tid; k < 32;   k += NTHR) sB2c[k] = b2c[k];

    // ---- P1: bucket insert + h0a channel r + output pos/batch copies ----
    const float px = pos[3 * i + 0];
    const float py = pos[3 * i + 1];
    const float pz = pos[3 * i + 2];
    const float si = fmaf(pz, pz, fmaf(py, py, px * px));
    const int bb = batch[i];
    const int cx0 = min(15, max(0, (int)(px * 16.0f)));
    const int cy0 = min(15, max(0, (int)(py * 16.0f)));
    const int cz0 = min(15, max(0, (int)(pz * 16.0f)));
    const int c = (bb << 12) | (cz0 << 8) | (cy0 << 4) | cx0;

    if (r == 0) {
        out[3 * i + 0] = px;
        out[3 * i + 1] = py;
        out[3 * i + 2] = pz;
        out[(size_t)NPTS * 35 + i] = (float)bb;
    } else if (r == 1) {
        const int slot = atomicAdd(&g_cell_cnt[c], 1);
        if (slot < CAPB)
            g_bucket[c * CAPB + slot] = make_float4(px, py, pz, __int_as_float(i));
    }
    {   // h0a channel r = pos @ W1a[0:3][:,r] + b1a[r]
        float s = b1a[r];
        s = fmaf(px, W1a[0 * 8 + r], s);
        s = fmaf(py, W1a[1 * 8 + r], s);
        s = fmaf(pz, W1a[2 * 8 + r], s);
        g_h0a[i * 8 + r] = s;
    }
    grid_barrier();

    // ---- P2: radius query (pass 1: record only) + channel-split layer a ----
    int cnt;
    {
        if (r == 0) s_cnt[p] = 0;
        __syncwarp();

        const int cb = c & 0xF000;

        // resolve this lane's <=4 cells and prefetch their counts (MLP=4)
        int cells[4], cnts[4];
#pragma unroll
        for (int t = 0; t < 4; ++t) {
            const int k = r + 8 * t;
            bool ok = (k < 27);
            const int z = cz0 + k / 9 - 1;
            const int y = cy0 + (k / 3) % 3 - 1;
            const int x = cx0 + k % 3 - 1;
            ok = ok && ((unsigned)(z | y | x) <= 15u);
            cells[t] = ok ? (cb | (z << 8) | (y << 4) | x) : 0;
            cnts[t]  = ok ? min(g_cell_cnt[cells[t]], CAPB) : 0;
        }

        // pass 1: d^2 test + record (accept branch is tiny)
#pragma unroll
        for (int t = 0; t < 4; ++t) {
            const int base = cells[t] * CAPB;
            for (int e = 0; e < cnts[t]; ++e) {
                const float4 q = g_bucket[base + e];
                const float sj  = fmaf(q.z, q.z, fmaf(q.y, q.y, q.x * q.x));
                const float dot = px * q.x + py * q.y + pz * q.z;
                const float d2  = si + sj - 2.0f * dot;   // reference's formula
                if (d2 <= R2) {
                    const int slot = atomicAdd(&s_cnt[p], 1);
                    if (slot < CAPN) {
                        s_nidx[p * CAPN + slot] = __float_as_int(q.w);
                        s_nrel[p * CAPN + slot] =
                            make_float4(q.x - px, q.y - py, q.z - pz, 0.0f);
                    }
                }
            }
        }
        __syncwarp();
        cnt = min(s_cnt[p], CAPN);

        // pass 2: lane r owns channel r; weights hoisted to registers
        const float wa0 = sWar[0 * 8 + r];
        const float wa1 = sWar[1 * 8 + r];
        const float wa2 = sWar[2 * 8 + r];
        float acc = -INFINITY;
        for (int n = 0; n < cnt; ++n) {
            const float4 rel = s_nrel[p * CAPN + n];
            const int j = s_nidx[p * CAPN + n];
            float h = g_h0a[j * 8 + r];              // coalesced 4B/lane
            h = fmaf(rel.x, wa0, h);
            h = fmaf(rel.y, wa1, h);
            h = fmaf(rel.z, wa2, h);
            acc = fmaxf(acc, fmaxf(h, 0.0f));
        }
        __syncwarp();

        // epilogue: v[r] = celu(acc_full @ W2a + b2a), acc gathered by shfl
        float v = sB2a[r];
#pragma unroll
        for (int m = 0; m < 8; ++m) {
            const float am = __shfl_sync(0xffffffffu, acc, m, 8);   // channel m
            v = fmaf(am, sW2a[m * 8 + r], v);
        }
        v = celu1(v);

        // h0b channels 2r, 2r+1 = b1b + v_full @ W1b[0:8]
        float h0 = sB1b[2 * r], h1 = sB1b[2 * r + 1];
#pragma unroll
        for (int o = 0; o < 8; ++o) {
            const float vo = __shfl_sync(0xffffffffu, v, o, 8);
            h0 = fmaf(vo, sWbx[o * 16 + 2 * r + 0], h0);
            h1 = fmaf(vo, sWbx[o * 16 + 2 * r + 1], h1);
        }
        *(float2*)&g_h0b[(size_t)i * 16 + 2 * r] = make_float2(h0, h1);
    }
    grid_barrier();

    // ---- P3: layer b (channel-split: lane owns channels 2r, 2r+1) ----
    {
        if (gtid < NCELL) g_cell_cnt[gtid] = 0;   // reset for next graph replay

        const float wb00 = sWbr[0 * 16 + 2 * r], wb01 = sWbr[0 * 16 + 2 * r + 1];
        const float wb10 = sWbr[1 * 16 + 2 * r], wb11 = sWbr[1 * 16 + 2 * r + 1];
        const float wb20 = sWbr[2 * 16 + 2 * r], wb21 = sWbr[2 * 16 + 2 * r + 1];

        float a0 = -INFINITY, a1 = -INFINITY;
        for (int n = 0; n < cnt; ++n) {
            const float4 rel = s_nrel[p * CAPN + n];
            const int j = s_nidx[p * CAPN + n];
            const float2 hb = *(const float2*)&g_h0b[(size_t)j * 16 + 2 * r];
            float h = hb.x;
            h = fmaf(rel.x, wb00, h);
            h = fmaf(rel.y, wb10, h);
            h = fmaf(rel.z, wb20, h);
            a0 = fmaxf(a0, fmaxf(h, 0.0f));
            h = hb.y;
            h = fmaf(rel.x, wb01, h);
            h = fmaf(rel.y, wb11, h);
            h = fmaf(rel.z, wb21, h);
            a1 = fmaxf(a1, fmaxf(h, 0.0f));
        }
        __syncwarp();

        // v[2r], v[2r+1] = celu(accfull @ W2b + b2b), accfull gathered by shfl
        float v0 = sB2b[2 * r], v1 = sB2b[2 * r + 1];
#pragma unroll
        for (int mm = 0; mm < 8; ++mm) {
            const float am0 = __shfl_sync(0xffffffffu, a0, mm, 8);  // ch 2mm
            const float am1 = __shfl_sync(0xffffffffu, a1, mm, 8);  // ch 2mm+1
            v0 = fmaf(am0, sW2b[(2 * mm + 0) * 16 + 2 * r + 0], v0);
            v0 = fmaf(am1, sW2b[(2 * mm + 1) * 16 + 2 * r + 0], v0);
            v1 = fmaf(am0, sW2b[(2 * mm + 0) * 16 + 2 * r + 1], v1);
            v1 = fmaf(am1, sW2b[(2 * mm + 1) * 16 + 2 * r + 1], v1);
        }
        v0 = celu1(v0);
        v1 = celu1(v1);

        // h0c channels 4r..4r+3 = b1c + v @ W1c[0:16]
        float c0 = sB1c[4 * r + 0], c1 = sB1c[4 * r + 1];
        float c2 = sB1c[4 * r + 2], c3 = sB1c[4 * r + 3];
#pragma unroll
        for (int oo = 0; oo < 8; ++oo) {
            const float w0 = __shfl_sync(0xffffffffu, v0, oo, 8);   // out 2oo
            const float w1 = __shfl_sync(0xffffffffu, v1, oo, 8);   // out 2oo+1
            c0 = fmaf(w0, sWcx[(2 * oo) * 32 + 4 * r + 0], c0);
            c1 = fmaf(w0, sWcx[(2 * oo) * 32 + 4 * r + 1], c1);
            c2 = fmaf(w0, sWcx[(2 * oo) * 32 + 4 * r + 2], c2);
            c3 = fmaf(w0, sWcx[(2 * oo) * 32 + 4 * r + 3], c3);
            c0 = fmaf(w1, sWcx[(2 * oo + 1) * 32 + 4 * r + 0], c0);
            c1 = fmaf(w1, sWcx[(2 * oo + 1) * 32 + 4 * r + 1], c1);
            c2 = fmaf(w1, sWcx[(2 * oo + 1) * 32 + 4 * r + 2], c2);
            c3 = fmaf(w1, sWcx[(2 * oo + 1) * 32 + 4 * r + 3], c3);
        }
        *(float4*)&g_h0c[(size_t)i * 32 + 4 * r] = make_float4(c0, c1, c2, c3);
    }
    grid_barrier();

    // ---- P4: layer c (channel-split: lane owns channels 4r..4r+3) ----
    {
        float wc[3][4];
#pragma unroll
        for (int d = 0; d < 3; ++d)
#pragma unroll
            for (int m = 0; m < 4; ++m) wc[d][m] = sWcr[d * 32 + 4 * r + m];

        float acc[4];
#pragma unroll
        for (int m = 0; m < 4; ++m) acc[m] = -INFINITY;

        for (int n = 0; n < cnt; ++n) {
            const float4 rel = s_nrel[p * CAPN + n];
            const int j = s_nidx[p * CAPN + n];
            const float4 hc = *(const float4*)&g_h0c[(size_t)j * 32 + 4 * r];
            const float hj[4] = {hc.x, hc.y, hc.z, hc.w};
#pragma unroll
            for (int m = 0; m < 4; ++m) {
                float h = hj[m];
                h = fmaf(rel.x, wc[0][m], h);
                h = fmaf(rel.y, wc[1][m], h);
                h = fmaf(rel.z, wc[2][m], h);
                acc[m] = fmaxf(acc[m], fmaxf(h, 0.0f));
            }
        }
        __syncwarp();

        float s0 = sB2c[4 * r + 0], s1 = sB2c[4 * r + 1];
        float s2 = sB2c[4 * r + 2], s3 = sB2c[4 * r + 3];
#pragma unroll
        for (int mm = 0; mm < 8; ++mm) {
            float am[4];
#pragma unroll
            for (int k = 0; k < 4; ++k)
                am[k] = __shfl_sync(0xffffffffu, acc[k], mm, 8);    // ch 4mm+k
#pragma unroll
            for (int k = 0; k < 4; ++k) {
                const int row = 4 * mm + k;
                s0 = fmaf(am[k], sW2c[row * 32 + 4 * r + 0], s0);
                s1 = fmaf(am[k], sW2c[row * 32 + 4 * r + 1], s1);
                s2 = fmaf(am[k], sW2c[row * 32 + 4 * r + 2], s2);
                s3 = fmaf(am[k], sW2c[row * 32 + 4 * r + 3], s3);
            }
        }
        float4* dst = (float4*)(out + (size_t)NPTS * 3 + (size_t)i * 32 + 4 * r);
        *dst = make_float4(celu1(s0), celu1(s1), celu1(s2), celu1(s3));
    }
}

// ---------------------------------------------------------------------------
// Launch. Inputs: 0 pos | 1 rgb (unused) | 2 batch |
//  3 W1a[6,8] 4 b1a 5 W2a 6 b2a | 7 W1b[11,16] 8 b1b 9 W2b 10 b2b
// 11 W1c[19,32] 12 b1c 13 W2c 14 b2c
// Output: [pos(3N) | feat(32N) | batch(N)] float32.
// ---------------------------------------------------------------------------
extern "C" void kernel_launch(void* const* d_in, const int* in_sizes, int n_in,
                              void* d_out, int out_size)
{
    fused_kernel<<<NBLK, NTHR>>>(
        (const float*)d_in[0], (const int*)d_in[2],
        (const float*)d_in[3],  (const float*)d_in[4],
        (const float*)d_in[5],  (const float*)d_in[6],
        (const float*)d_in[7],  (const float*)d_in[8],
        (const float*)d_in[9],  (const float*)d_in[10],
        (const float*)d_in[11], (const float*)d_in[12],
        (const float*)d_in[13], (const float*)d_in[14],
        (float*)d_out);
}